// round 7
// baseline (speedup 1.0000x reference)
#include <cuda_runtime.h>
#include <cuda_fp16.h>
#include <cstdint>

#define NN 50000
#define EE 800000
#define RR 6
#define FF 128
#define SEG (RR * NN)

// ---------------- scratch (static device globals; no allocations) ----------------
__device__ __align__(16) float g_v1[RR * FF];
__device__ __align__(16) float g_v2[RR * FF];
__device__ __align__(16) __half g_Wh[RR * FF * FF];        // [r][o][f] = W[r][f][o] fp16
__device__ __align__(16) __half g_Wc1h[FF * FF];           // [o][k] fp16
__device__ __align__(16) __half g_Wc2h[FF * FF];
__device__ __align__(16) int g_cnt[SEG];
__device__ __align__(16) int g_off[SEG];
__device__ __align__(16) int g_cur[SEG];
__device__ __align__(16) int g_bsum[1024];
__device__ __align__(16) int g_src_sorted[EE];

__device__ __forceinline__ void cpa16(void* dst_smem, const void* src) {
    uint32_t d = (uint32_t)__cvta_generic_to_shared(dst_smem);
    asm volatile("cp.async.cg.shared.global [%0], [%1], 16;" :: "r"(d), "l"(src));
}

// ---------------- K0: precompute v1,v2 and fp16 W^T per relation ----------------
__global__ void precompute_kernel(const float* __restrict__ W,
                                  const float* __restrict__ att1,
                                  const float* __restrict__ att2) {
    __shared__ float red1[128];
    __shared__ float red2[128];
    int rf = blockIdx.x;           // r*128 + f
    int r  = rf >> 7, f = rf & 127;
    int o  = threadIdx.x;
    float w = W[rf * 128 + o];
    g_Wh[(size_t)r * (FF * FF) + o * FF + f] = __float2half_rn(w);

    red1[o] = w * att1[o];
    red2[o] = w * att2[o];
    __syncthreads();
    for (int s = 64; s > 0; s >>= 1) {
        if (o < s) { red1[o] += red1[o + s]; red2[o] += red2[o + s]; }
        __syncthreads();
    }
    if (o == 0) { g_v1[rf] = red1[0]; g_v2[rf] = red2[0]; }
}

__global__ void wc_convert_kernel(const float* __restrict__ Wc) {
    int o = blockIdx.x, k = threadIdx.x;
    g_Wc1h[o * FF + k] = __float2half_rn(Wc[o * 256 + k]);
    g_Wc2h[o * FF + k] = __float2half_rn(Wc[o * 256 + 128 + k]);
}

// ---------------- CSR build ----------------
__global__ void zero_cnt_kernel() {
    int i = blockIdx.x * blockDim.x + threadIdx.x;
    if (i < SEG) g_cnt[i] = 0;
}
__global__ void hist_kernel(const int* __restrict__ edst, const int* __restrict__ erel) {
    int i = blockIdx.x * blockDim.x + threadIdx.x;
    if (i >= EE) return;
    atomicAdd(&g_cnt[erel[i] * NN + edst[i]], 1);
}
__global__ void scan1_kernel() {
    __shared__ int sm[512];
    int tid = threadIdx.x;
    int idx = blockIdx.x * 512 + tid;
    int v = (idx < SEG) ? g_cnt[idx] : 0;
    sm[tid] = v;
    __syncthreads();
#pragma unroll
    for (int s = 1; s < 512; s <<= 1) {
        int add = (tid >= s) ? sm[tid - s] : 0;
        __syncthreads();
        sm[tid] += add;
        __syncthreads();
    }
    int incl = sm[tid];
    if (idx < SEG) g_off[idx] = incl - v;
    if (tid == 511) g_bsum[blockIdx.x] = incl;
}
__global__ void scan2_kernel(int nblk) {
    __shared__ int sm[1024];
    int tid = threadIdx.x;
    int v = (tid < nblk) ? g_bsum[tid] : 0;
    sm[tid] = v;
    __syncthreads();
#pragma unroll
    for (int s = 1; s < 1024; s <<= 1) {
        int add = (tid >= s) ? sm[tid - s] : 0;
        __syncthreads();
        sm[tid] += add;
        __syncthreads();
    }
    if (tid < nblk) g_bsum[tid] = sm[tid] - v;
}
__global__ void scan3_kernel() {
    int idx = blockIdx.x * blockDim.x + threadIdx.x;
    if (idx >= SEG) return;
    int o = g_off[idx] + g_bsum[idx >> 9];
    g_off[idx] = o;
    g_cur[idx] = o;
}
__global__ void permute_kernel(const int* __restrict__ esrc,
                               const int* __restrict__ edst,
                               const int* __restrict__ erel) {
    int i = blockIdx.x * blockDim.x + threadIdx.x;
    if (i >= EE) return;
    int key = erel[i] * NN + edst[i];
    int pos = atomicAdd(&g_cur[key], 1);
    g_src_sorted[pos] = esrc[i];
}

// ---------------- megakernel: gather + softmax + factored GEMM ----------------
__device__ __forceinline__ void mma16(float d[4], uint32_t a0, uint32_t a1, uint32_t a2, uint32_t a3,
                                      uint32_t b0, uint32_t b1) {
    asm volatile(
        "mma.sync.aligned.m16n8k16.row.col.f32.f16.f16.f32 "
        "{%0,%1,%2,%3},{%4,%5,%6,%7},{%8,%9},{%0,%1,%2,%3};"
        : "+f"(d[0]), "+f"(d[1]), "+f"(d[2]), "+f"(d[3])
        : "r"(a0), "r"(a1), "r"(a2), "r"(a3), "r"(b0), "r"(b1));
}

#define STR 136
#define AGG_OFF 0                        // half idx: [6][32][STR]
#define WT_OFF (6 * 32 * STR)            // [128][STR]
#define FLT_OFF (WT_OFF + 128 * STR)     // float region begins (half idx)
// float region layout (float idx from FLT_OFF/2... use pointer):
// v1s[768] v2s[768] es1[192] es2[192] ds[192] c1s[192] c2s[192] bcs[128]
#define MEGA_SMEM (FLT_OFF * 2 + (768 + 768 + 192 * 5 + 128) * 4)   // 97536 B

__global__ __launch_bounds__(256, 2) void mega_kernel(const float* __restrict__ node_h,
                                                      const float* __restrict__ bc,
                                                      float* __restrict__ out) {
    extern __shared__ __half sh[];
    float* fr  = reinterpret_cast<float*>(sh + FLT_OFF);
    float* v1s = fr;
    float* v2s = fr + 768;
    float* es1 = fr + 1536;
    float* es2 = fr + 1728;
    float* ds  = fr + 1920;
    float* c1s = fr + 2112;
    float* c2s = fr + 2304;
    float* bcs = fr + 2496;

    int n0 = blockIdx.x * 32;
    int t = threadIdx.x;
    int warp = t >> 5, lane = t & 31;
    int g = lane >> 2, tg = lane & 3;

    // ---- prefetch W[0] (cp.async) + load v1/v2/bc
    {
#pragma unroll
        for (int j = 0; j < 8; j++) {
            int lin = t + 256 * j;
            int o = lin >> 4;
            int c8 = (lin & 15) * 8;
            cpa16(sh + WT_OFF + o * STR + c8, g_Wh + o * FF + c8);
        }
        asm volatile("cp.async.commit_group;" ::: "memory");
#pragma unroll
        for (int j = 0; j < 3; j++) {
            int i = t + 256 * j;
            v1s[i] = g_v1[i];
            v2s[i] = g_v2[i];
        }
        if (t < 128) bcs[t] = 6.0f * bc[t];
    }
    __syncthreads();

    // ---- gather phase: 192 segments, warp-per-segment
    for (int i = 0; i < 24; i++) {
        int s = warp + 8 * i;          // 0..191
        int r = s >> 5, row = s & 31;
        int n = n0 + row;
        __half2* dst = reinterpret_cast<__half2*>(sh + AGG_OFF + (r * 32 + row) * STR + lane * 4);
        if (n >= NN) {
            __half2 z = __floats2half2_rn(0.f, 0.f);
            dst[0] = z; dst[1] = z;
            if (lane == 0) { es1[row * 6 + r] = 0.f; es2[row * 6 + r] = 0.f; ds[row * 6 + r] = 1.f; }
            continue;
        }
        int key = r * NN + n;
        int off = g_off[key];
        int deg = g_cnt[key];
        const float4* h4 = reinterpret_cast<const float4*>(node_h);
        float4 acc = make_float4(0.f, 0.f, 0.f, 0.f);
        int e = 0;
        for (; e + 2 <= deg; e += 2) {
            int i0 = g_src_sorted[off + e];
            int i1 = g_src_sorted[off + e + 1];
            float4 a = h4[(size_t)i0 * 32 + lane];
            float4 b = h4[(size_t)i1 * 32 + lane];
            acc.x += a.x + b.x; acc.y += a.y + b.y;
            acc.z += a.z + b.z; acc.w += a.w + b.w;
        }
        if (e < deg) {
            int i0 = g_src_sorted[off + e];
            float4 a = h4[(size_t)i0 * 32 + lane];
            acc.x += a.x; acc.y += a.y; acc.z += a.z; acc.w += a.w;
        }
        dst[0] = __floats2half2_rn(acc.x, acc.y);
        dst[1] = __floats2half2_rn(acc.z, acc.w);

        const float* w1 = v1s + r * 128 + lane * 4;
        const float* w2 = v2s + r * 128 + lane * 4;
        float p1 = acc.x * w1[0] + acc.y * w1[1] + acc.z * w1[2] + acc.w * w1[3];
        float p2 = acc.x * w2[0] + acc.y * w2[1] + acc.z * w2[2] + acc.w * w2[3];
#pragma unroll
        for (int sft = 16; sft > 0; sft >>= 1) {
            p1 += __shfl_xor_sync(0xffffffffu, p1, sft);
            p2 += __shfl_xor_sync(0xffffffffu, p2, sft);
        }
        if (lane == 0) {
            es1[row * 6 + r] = p1;
            es2[row * 6 + r] = p2;
            ds[row * 6 + r] = 1.0f + (float)deg;
        }
    }
    __syncthreads();

    // ---- softmax (threads 0..31, one per node)
    if (t < 32) {
        int row = t;
        float e1[RR], e2[RR], dg[RR];
#pragma unroll
        for (int r = 0; r < RR; r++) {
            dg[r] = ds[row * 6 + r];
            e1[r] = es1[row * 6 + r] / dg[r];
            e2[r] = es2[row * 6 + r] / dg[r];
        }
        float m1 = e1[0], m2 = e2[0];
#pragma unroll
        for (int r = 1; r < RR; r++) { m1 = fmaxf(m1, e1[r]); m2 = fmaxf(m2, e2[r]); }
        float s1 = 0.f, s2 = 0.f;
#pragma unroll
        for (int r = 0; r < RR; r++) {
            e1[r] = __expf(e1[r] - m1); s1 += e1[r];
            e2[r] = __expf(e2[r] - m2); s2 += e2[r];
        }
        float i1 = 1.0f / s1, i2 = 1.0f / s2;
#pragma unroll
        for (int r = 0; r < RR; r++) {
            c1s[row * 6 + r] = e1[r] * i1 / dg[r];
            c2s[row * 6 + r] = e2[r] * i2 / dg[r];
        }
    }
    __syncthreads();

    // ---- GEMM warp layout: 2x4 warps, warp tile 16 rows x 32 cols
    int wm = warp >> 2, wn = warp & 3;
    int rowloc = wm * 16 + g;

    float P[4][4], Y[4][4], Z[4][4];
#pragma unroll
    for (int ni = 0; ni < 4; ni++)
#pragma unroll
        for (int j = 0; j < 4; j++) { P[ni][j] = 0.f; Y[ni][j] = 0.f; Z[ni][j] = 0.f; }

    auto mmastep = [&](const __half* Abase, const __half* Bbase) {
#pragma unroll
        for (int ks = 0; ks < 8; ks++) {
            int k0 = ks * 16;
            const __half* ap = Abase + rowloc * STR + k0 + tg * 2;
            uint32_t a0 = *reinterpret_cast<const uint32_t*>(ap);
            uint32_t a1 = *reinterpret_cast<const uint32_t*>(ap + 8 * STR);
            uint32_t a2 = *reinterpret_cast<const uint32_t*>(ap + 8);
            uint32_t a3 = *reinterpret_cast<const uint32_t*>(ap + 8 * STR + 8);
            uint32_t b[4][2];
#pragma unroll
            for (int ni = 0; ni < 4; ni++) {
                const __half* bp = Bbase + (wn * 32 + ni * 8 + g) * STR + k0 + tg * 2;
                b[ni][0] = *reinterpret_cast<const uint32_t*>(bp);
                b[ni][1] = *reinterpret_cast<const uint32_t*>(bp + 8);
            }
#pragma unroll
            for (int ni = 0; ni < 4; ni++)
                mma16(P[ni], a0, a1, a2, a3, b[ni][0], b[ni][1]);
        }
    };

    // ---- stage 1: per relation r, P = Agg[r]@W[r]; fold into Y,Z
    for (int r = 0; r < RR; r++) {
        asm volatile("cp.async.wait_group 0;" ::: "memory");
        __syncthreads();
        mmastep(sh + AGG_OFF + r * 32 * STR, sh + WT_OFF);
        __syncthreads();   // all warps done reading Wt
        // issue next weight tile loads
        if (r < 5) {
#pragma unroll
            for (int j = 0; j < 8; j++) {
                int lin = t + 256 * j;
                int o = lin >> 4;
                int c8 = (lin & 15) * 8;
                cpa16(sh + WT_OFF + o * STR + c8, g_Wh + (size_t)(r + 1) * (FF * FF) + o * FF + c8);
            }
            asm volatile("cp.async.commit_group;" ::: "memory");
        } else {
            // Wc1 -> Wt ; Wc2 -> Agg[2..5] region
#pragma unroll
            for (int j = 0; j < 8; j++) {
                int lin = t + 256 * j;
                int o = lin >> 4;
                int c8 = (lin & 15) * 8;
                cpa16(sh + WT_OFF + o * STR + c8, g_Wc1h + o * FF + c8);
                cpa16(sh + AGG_OFF + 2 * 32 * STR + o * STR + c8, g_Wc2h + o * FF + c8);
            }
            asm volatile("cp.async.commit_group;" ::: "memory");
        }
        // fold
        int ra = n0 + rowloc, rb = ra + 8;
        float c1a = (ra < NN) ? c1s[rowloc * 6 + r] : 0.f;
        float c1b = (rb < NN) ? c1s[(rowloc + 8) * 6 + r] : 0.f;
        float c2a = (ra < NN) ? c2s[rowloc * 6 + r] : 0.f;
        float c2b = (rb < NN) ? c2s[(rowloc + 8) * 6 + r] : 0.f;
#pragma unroll
        for (int ni = 0; ni < 4; ni++) {
            Y[ni][0] += c1a * P[ni][0]; Y[ni][1] += c1a * P[ni][1];
            Y[ni][2] += c1b * P[ni][2]; Y[ni][3] += c1b * P[ni][3];
            Z[ni][0] += c2a * P[ni][0]; Z[ni][1] += c2a * P[ni][1];
            Z[ni][2] += c2b * P[ni][2]; Z[ni][3] += c2b * P[ni][3];
            P[ni][0] = 0.f; P[ni][1] = 0.f; P[ni][2] = 0.f; P[ni][3] = 0.f;
        }
    }

    // ---- write Y,Z fp16 into Agg[0],Agg[1] regions
    __half* Yt = sh + AGG_OFF;              // [32][STR]
    __half* Zt = sh + AGG_OFF + 32 * STR;
#pragma unroll
    for (int ni = 0; ni < 4; ni++) {
        int col = wn * 32 + ni * 8 + tg * 2;
        *reinterpret_cast<__half2*>(Yt + rowloc * STR + col) = __floats2half2_rn(Y[ni][0], Y[ni][1]);
        *reinterpret_cast<__half2*>(Yt + (rowloc + 8) * STR + col) = __floats2half2_rn(Y[ni][2], Y[ni][3]);
        *reinterpret_cast<__half2*>(Zt + rowloc * STR + col) = __floats2half2_rn(Z[ni][0], Z[ni][1]);
        *reinterpret_cast<__half2*>(Zt + (rowloc + 8) * STR + col) = __floats2half2_rn(Z[ni][2], Z[ni][3]);
    }
    asm volatile("cp.async.wait_group 0;" ::: "memory");
    __syncthreads();

    // ---- stage 2: out = Y@Wc1^T + Z@Wc2^T + 6*bc
    mmastep(Yt, sh + WT_OFF);
    mmastep(Zt, sh + AGG_OFF + 2 * 32 * STR);

    int ra = n0 + rowloc, rb = ra + 8;
#pragma unroll
    for (int ni = 0; ni < 4; ni++) {
        int col = wn * 32 + ni * 8 + tg * 2;
        float b0 = bcs[col], b1 = bcs[col + 1];
        if (ra < NN) {
            float2 v = make_float2(P[ni][0] + b0, P[ni][1] + b1);
            *reinterpret_cast<float2*>(&out[(size_t)ra * FF + col]) = v;
        }
        if (rb < NN) {
            float2 v = make_float2(P[ni][2] + b0, P[ni][3] + b1);
            *reinterpret_cast<float2*>(&out[(size_t)rb * FF + col]) = v;
        }
    }
}

// ---------------- launch ----------------
extern "C" void kernel_launch(void* const* d_in, const int* in_sizes, int n_in,
                              void* d_out, int out_size) {
    const float* node_h = (const float*)d_in[0];
    const float* W      = (const float*)d_in[1];
    const float* att1   = (const float*)d_in[2];
    const float* att2   = (const float*)d_in[3];
    const float* Wc     = (const float*)d_in[4];
    const float* bc     = (const float*)d_in[5];
    const int*   esrc   = (const int*)d_in[6];
    const int*   edst   = (const int*)d_in[7];
    const int*   erel   = (const int*)d_in[8];
    float* out = (float*)d_out;

    static int smem_set = 0;
    if (!smem_set) {
        cudaFuncSetAttribute(mega_kernel, cudaFuncAttributeMaxDynamicSharedMemorySize, MEGA_SMEM);
        smem_set = 1;
    }

    const int nblk1 = (SEG + 511) / 512;

    precompute_kernel<<<RR * FF, 128>>>(W, att1, att2);
    wc_convert_kernel<<<FF, 128>>>(Wc);
    zero_cnt_kernel<<<(SEG + 255) / 256, 256>>>();
    hist_kernel<<<(EE + 255) / 256, 256>>>(edst, erel);
    scan1_kernel<<<nblk1, 512>>>();
    scan2_kernel<<<1, 1024>>>(nblk1);
    scan3_kernel<<<(SEG + 255) / 256, 256>>>();
    permute_kernel<<<(EE + 255) / 256, 256>>>(esrc, edst, erel);
    mega_kernel<<<(NN + 31) / 32, 256, MEGA_SMEM>>>(node_h, bc, out);

    if (out_size >= NN * FF + RR * FF * FF) {
        cudaMemcpyAsync(out + (size_t)NN * FF, W,
                        sizeof(float) * RR * FF * FF, cudaMemcpyDeviceToDevice, 0);
    }
}

// round 8
// speedup vs baseline: 1.2580x; 1.2580x over previous
#include <cuda_runtime.h>
#include <cuda_fp16.h>
#include <cstdint>

#define NN 50000
#define EE 800000
#define RR 6
#define FF 128
#define SEG (RR * NN)

// ---------------- scratch (static device globals; no allocations) ----------------
__device__ __align__(16) __half g_nodeH[(size_t)NN * FF];  // 12.8 MB fp16 node_h
__device__ __align__(16) __half g_aggH[(size_t)SEG * FF];  // 76.8 MB fp16 agg
__device__ __align__(16) float g_c1[NN * RR];
__device__ __align__(16) float g_c2[NN * RR];
__device__ __align__(16) float g_v1[RR * FF];
__device__ __align__(16) float g_v2[RR * FF];
__device__ __align__(16) __half g_Wh[RR * FF * FF];        // [r][o][f] = W[r][f][o] fp16
__device__ __align__(16) __half g_Wc1h[FF * FF];           // [o][k] fp16
__device__ __align__(16) __half g_Wc2h[FF * FF];
__device__ __align__(16) float g_e1[SEG];
__device__ __align__(16) float g_e2[SEG];
__device__ __align__(16) int g_cnt[SEG];
__device__ __align__(16) int g_off[SEG];
__device__ __align__(16) int g_cur[SEG];
__device__ __align__(16) int g_bsum[1024];
__device__ __align__(16) int g_src_sorted[EE];

__device__ __forceinline__ void cpa16(void* dst_smem, const void* src) {
    uint32_t d = (uint32_t)__cvta_generic_to_shared(dst_smem);
    asm volatile("cp.async.cg.shared.global [%0], [%1], 16;" :: "r"(d), "l"(src));
}

// ---------------- K0: precompute v1,v2 and fp16 W^T per relation ----------------
__global__ void precompute_kernel(const float* __restrict__ W,
                                  const float* __restrict__ att1,
                                  const float* __restrict__ att2) {
    __shared__ float red1[128];
    __shared__ float red2[128];
    int rf = blockIdx.x;           // r*128 + f
    int r  = rf >> 7, f = rf & 127;
    int o  = threadIdx.x;
    float w = W[rf * 128 + o];
    g_Wh[(size_t)r * (FF * FF) + o * FF + f] = __float2half_rn(w);

    red1[o] = w * att1[o];
    red2[o] = w * att2[o];
    __syncthreads();
    for (int s = 64; s > 0; s >>= 1) {
        if (o < s) { red1[o] += red1[o + s]; red2[o] += red2[o + s]; }
        __syncthreads();
    }
    if (o == 0) { g_v1[rf] = red1[0]; g_v2[rf] = red2[0]; }
}

__global__ void wc_convert_kernel(const float* __restrict__ Wc) {
    int o = blockIdx.x, k = threadIdx.x;
    g_Wc1h[o * FF + k] = __float2half_rn(Wc[o * 256 + k]);
    g_Wc2h[o * FF + k] = __float2half_rn(Wc[o * 256 + 128 + k]);
}

// ---------------- convert node_h -> fp16 (halves gather L2 traffic) ----------------
__global__ void nodeh_convert_kernel(const float* __restrict__ node_h) {
    size_t i = (size_t)blockIdx.x * blockDim.x + threadIdx.x;   // one per 8 elems
    if (i >= (size_t)NN * FF / 8) return;
    const float4* p = reinterpret_cast<const float4*>(node_h) + i * 2;
    float4 a = p[0], b = p[1];
    __half2 h0 = __floats2half2_rn(a.x, a.y);
    __half2 h1 = __floats2half2_rn(a.z, a.w);
    __half2 h2 = __floats2half2_rn(b.x, b.y);
    __half2 h3 = __floats2half2_rn(b.z, b.w);
    uint4 o;
    o.x = *reinterpret_cast<uint32_t*>(&h0);
    o.y = *reinterpret_cast<uint32_t*>(&h1);
    o.z = *reinterpret_cast<uint32_t*>(&h2);
    o.w = *reinterpret_cast<uint32_t*>(&h3);
    reinterpret_cast<uint4*>(g_nodeH)[i] = o;
}

// ---------------- CSR build ----------------
__global__ void zero_cnt_kernel() {
    int i = blockIdx.x * blockDim.x + threadIdx.x;
    if (i < SEG) g_cnt[i] = 0;
}
__global__ void hist_kernel(const int* __restrict__ edst, const int* __restrict__ erel) {
    int i = blockIdx.x * blockDim.x + threadIdx.x;
    if (i >= EE) return;
    atomicAdd(&g_cnt[erel[i] * NN + edst[i]], 1);
}
__global__ void scan1_kernel() {
    __shared__ int sm[512];
    int tid = threadIdx.x;
    int idx = blockIdx.x * 512 + tid;
    int v = (idx < SEG) ? g_cnt[idx] : 0;
    sm[tid] = v;
    __syncthreads();
#pragma unroll
    for (int s = 1; s < 512; s <<= 1) {
        int add = (tid >= s) ? sm[tid - s] : 0;
        __syncthreads();
        sm[tid] += add;
        __syncthreads();
    }
    int incl = sm[tid];
    if (idx < SEG) g_off[idx] = incl - v;
    if (tid == 511) g_bsum[blockIdx.x] = incl;
}
__global__ void scan2_kernel(int nblk) {
    __shared__ int sm[1024];
    int tid = threadIdx.x;
    int v = (tid < nblk) ? g_bsum[tid] : 0;
    sm[tid] = v;
    __syncthreads();
#pragma unroll
    for (int s = 1; s < 1024; s <<= 1) {
        int add = (tid >= s) ? sm[tid - s] : 0;
        __syncthreads();
        sm[tid] += add;
        __syncthreads();
    }
    if (tid < nblk) g_bsum[tid] = sm[tid] - v;
}
__global__ void scan3_kernel() {
    int idx = blockIdx.x * blockDim.x + threadIdx.x;
    if (idx >= SEG) return;
    int o = g_off[idx] + g_bsum[idx >> 9];
    g_off[idx] = o;
    g_cur[idx] = o;
}
__global__ void permute_kernel(const int* __restrict__ esrc,
                               const int* __restrict__ edst,
                               const int* __restrict__ erel) {
    int i = blockIdx.x * blockDim.x + threadIdx.x;
    if (i >= EE) return;
    int key = erel[i] * NN + edst[i];
    int pos = atomicAdd(&g_cur[key], 1);
    g_src_sorted[pos] = esrc[i];
}

// ---------------- gather: one warp per (rel,dst) segment; fp16 in, fp16 out ----------------
__global__ __launch_bounds__(256) void gather_kernel() {
    int seg = blockIdx.x * 8 + (threadIdx.x >> 5);
    if (seg >= SEG) return;
    int l = threadIdx.x & 31;
    int r = seg / NN;
    int off = g_off[seg];
    int deg = g_cnt[seg];

    const uint2* h2 = reinterpret_cast<const uint2*>(g_nodeH);   // 32 x uint2 per row
    float4 acc = make_float4(0.f, 0.f, 0.f, 0.f);
    int e = 0;
    for (; e + 2 <= deg; e += 2) {
        int i0 = g_src_sorted[off + e];
        int i1 = g_src_sorted[off + e + 1];
        uint2 ua = h2[(size_t)i0 * 32 + l];
        uint2 ub = h2[(size_t)i1 * 32 + l];
        float2 a0 = __half22float2(*reinterpret_cast<__half2*>(&ua.x));
        float2 a1 = __half22float2(*reinterpret_cast<__half2*>(&ua.y));
        float2 b0 = __half22float2(*reinterpret_cast<__half2*>(&ub.x));
        float2 b1 = __half22float2(*reinterpret_cast<__half2*>(&ub.y));
        acc.x += a0.x + b0.x; acc.y += a0.y + b0.y;
        acc.z += a1.x + b1.x; acc.w += a1.y + b1.y;
    }
    if (e < deg) {
        int i0 = g_src_sorted[off + e];
        uint2 ua = h2[(size_t)i0 * 32 + l];
        float2 a0 = __half22float2(*reinterpret_cast<__half2*>(&ua.x));
        float2 a1 = __half22float2(*reinterpret_cast<__half2*>(&ua.y));
        acc.x += a0.x; acc.y += a0.y; acc.z += a1.x; acc.w += a1.y;
    }

    __half2 h01 = __floats2half2_rn(acc.x, acc.y);
    __half2 h23 = __floats2half2_rn(acc.z, acc.w);
    uint2 packed;
    packed.x = *reinterpret_cast<uint32_t*>(&h01);
    packed.y = *reinterpret_cast<uint32_t*>(&h23);
    reinterpret_cast<uint2*>(g_aggH)[(size_t)seg * 32 + l] = packed;

    float4 w1 = reinterpret_cast<const float4*>(g_v1)[r * 32 + l];
    float4 w2 = reinterpret_cast<const float4*>(g_v2)[r * 32 + l];
    float p1 = acc.x * w1.x + acc.y * w1.y + acc.z * w1.z + acc.w * w1.w;
    float p2 = acc.x * w2.x + acc.y * w2.y + acc.z * w2.z + acc.w * w2.w;
#pragma unroll
    for (int s = 16; s > 0; s >>= 1) {
        p1 += __shfl_xor_sync(0xffffffffu, p1, s);
        p2 += __shfl_xor_sync(0xffffffffu, p2, s);
    }
    if (l == 0) { g_e1[seg] = p1; g_e2[seg] = p2; }
}

// ---------------- per-node softmax -> c1,c2 ----------------
__global__ void softmax_kernel() {
    int n = blockIdx.x * blockDim.x + threadIdx.x;
    if (n >= NN) return;
    float e1[RR], e2[RR], dg[RR];
#pragma unroll
    for (int r = 0; r < RR; r++) {
        dg[r] = 1.0f + (float)g_cnt[r * NN + n];
        e1[r] = g_e1[r * NN + n] / dg[r];
        e2[r] = g_e2[r * NN + n] / dg[r];
    }
    float m1 = e1[0], m2 = e2[0];
#pragma unroll
    for (int r = 1; r < RR; r++) { m1 = fmaxf(m1, e1[r]); m2 = fmaxf(m2, e2[r]); }
    float s1 = 0.f, s2 = 0.f;
#pragma unroll
    for (int r = 0; r < RR; r++) {
        e1[r] = __expf(e1[r] - m1); s1 += e1[r];
        e2[r] = __expf(e2[r] - m2); s2 += e2[r];
    }
    float i1 = 1.0f / s1, i2 = 1.0f / s2;
#pragma unroll
    for (int r = 0; r < RR; r++) {
        g_c1[n * RR + r] = e1[r] * i1 / dg[r];
        g_c2[n * RR + r] = e2[r] * i2 / dg[r];
    }
}

// ---------------- K4: fused factored GEMM ----------------
// Stage 1 per r: P_r = aggH[r] @ Wh[r]  (64x128, K=128);  Y += c1*P_r, Z += c2*P_r
// Stage 2: out = Y@Wc1^T + Z@Wc2^T + 6*bc
__device__ __forceinline__ void mma16(float d[4], uint32_t a0, uint32_t a1, uint32_t a2, uint32_t a3,
                                      uint32_t b0, uint32_t b1) {
    asm volatile(
        "mma.sync.aligned.m16n8k16.row.col.f32.f16.f16.f32 "
        "{%0,%1,%2,%3},{%4,%5,%6,%7},{%8,%9},{%0,%1,%2,%3};"
        : "+f"(d[0]), "+f"(d[1]), "+f"(d[2]), "+f"(d[3])
        : "r"(a0), "r"(a1), "r"(a2), "r"(a3), "r"(b0), "r"(b1));
}

#define STR 136
#define AH_OFF 0
#define BW_OFF (2 * 64 * STR)
#define YZ_OFF (BW_OFF + 2 * 128 * STR)
#define WC2_OFF (YZ_OFF + 2 * 64 * STR)
#define GEMM_SMEM ((WC2_OFF + 128 * STR) * 2)   // 174080 bytes

__global__ __launch_bounds__(256, 1) void gemm_kernel(float* __restrict__ out,
                                                      const float* __restrict__ bc) {
    extern __shared__ __half sh[];
    __half* Ah   = sh + AH_OFF;    // [2][64][STR]
    __half* Bw   = sh + BW_OFF;    // [2][128][STR]  (stage 6 loads Wc1 into buf 0)
    __half* Yz   = sh + YZ_OFF;    // [2][64][STR]
    __half* Wc2s = sh + WC2_OFF;   // [128][STR]

    int n0 = blockIdx.x * 64;
    int t = threadIdx.x;
    int warp = t >> 5, lane = t & 31;
    int wm = warp >> 2, wn = warp & 3;   // 2x4 warps, warp tile 32 rows x 32 cols
    int g = lane >> 2, tg = lane & 3;

    float P[2][4][4], Y[2][4][4], Z[2][4][4];
#pragma unroll
    for (int mi = 0; mi < 2; mi++)
#pragma unroll
        for (int ni = 0; ni < 4; ni++)
#pragma unroll
            for (int j = 0; j < 4; j++) { P[mi][ni][j] = 0.f; Y[mi][ni][j] = 0.f; Z[mi][ni][j] = 0.f; }

    auto ldstage = [&](int s) {
        if (s < 6) {
            int buf = s & 1;
#pragma unroll
            for (int j = 0; j < 4; j++) {                 // A tile: 64x128 halves
                int lin = t + 256 * j;
                int row = lin >> 4;
                int c8 = (lin & 15) * 8;
                int n = n0 + row;
                if (n >= NN) n = 0;
                cpa16(Ah + buf * 64 * STR + row * STR + c8,
                      g_aggH + ((size_t)s * NN + n) * FF + c8);
            }
#pragma unroll
            for (int j = 0; j < 8; j++) {                 // W tile: 128x128 halves
                int lin = t + 256 * j;
                int o = lin >> 4;
                int c8 = (lin & 15) * 8;
                cpa16(Bw + buf * 128 * STR + o * STR + c8,
                      g_Wh + (size_t)s * (FF * FF) + o * FF + c8);
            }
        } else {
#pragma unroll
            for (int j = 0; j < 8; j++) {                 // Wc1 -> Bw[0]
                int lin = t + 256 * j;
                int o = lin >> 4;
                int c8 = (lin & 15) * 8;
                cpa16(Bw + o * STR + c8, g_Wc1h + o * FF + c8);
            }
#pragma unroll
            for (int j = 0; j < 8; j++) {                 // Wc2 -> Wc2s
                int lin = t + 256 * j;
                int o = lin >> 4;
                int c8 = (lin & 15) * 8;
                cpa16(Wc2s + o * STR + c8, g_Wc2h + o * FF + c8);
            }
        }
        asm volatile("cp.async.commit_group;" ::: "memory");
    };

    auto mmastep = [&](const __half* Abase, const __half* Bbase) {
#pragma unroll
        for (int ks = 0; ks < 8; ks++) {
            int k0 = ks * 16;
            uint32_t a[2][4];
#pragma unroll
            for (int mi = 0; mi < 2; mi++) {
                const __half* ap = Abase + (wm * 32 + mi * 16 + g) * STR + k0 + tg * 2;
                a[mi][0] = *reinterpret_cast<const uint32_t*>(ap);
                a[mi][1] = *reinterpret_cast<const uint32_t*>(ap + 8 * STR);
                a[mi][2] = *reinterpret_cast<const uint32_t*>(ap + 8);
                a[mi][3] = *reinterpret_cast<const uint32_t*>(ap + 8 * STR + 8);
            }
            uint32_t b[4][2];
#pragma unroll
            for (int ni = 0; ni < 4; ni++) {
                const __half* bp = Bbase + (wn * 32 + ni * 8 + g) * STR + k0 + tg * 2;
                b[ni][0] = *reinterpret_cast<const uint32_t*>(bp);
                b[ni][1] = *reinterpret_cast<const uint32_t*>(bp + 8);
            }
#pragma unroll
            for (int mi = 0; mi < 2; mi++)
#pragma unroll
                for (int ni = 0; ni < 4; ni++)
                    mma16(P[mi][ni], a[mi][0], a[mi][1], a[mi][2], a[mi][3],
                          b[ni][0], b[ni][1]);
        }
    };

    ldstage(0);
    ldstage(1);

    for (int s = 0; s < 6; s++) {
        asm volatile("cp.async.wait_group 1;" ::: "memory");
        __syncthreads();
        int buf = s & 1;
        mmastep(Ah + buf * 64 * STR, Bw + buf * 128 * STR);
        // fold P into Y, Z with per-(node, r) coefficients
#pragma unroll
        for (int mi = 0; mi < 2; mi++) {
            int ra = n0 + wm * 32 + mi * 16 + g;
            int rb = ra + 8;
            float c1a = (ra < NN) ? g_c1[ra * RR + s] : 0.f;
            float c1b = (rb < NN) ? g_c1[rb * RR + s] : 0.f;
            float c2a = (ra < NN) ? g_c2[ra * RR + s] : 0.f;
            float c2b = (rb < NN) ? g_c2[rb * RR + s] : 0.f;
#pragma unroll
            for (int ni = 0; ni < 4; ni++) {
                Y[mi][ni][0] += c1a * P[mi][ni][0];
                Y[mi][ni][1] += c1a * P[mi][ni][1];
                Y[mi][ni][2] += c1b * P[mi][ni][2];
                Y[mi][ni][3] += c1b * P[mi][ni][3];
                Z[mi][ni][0] += c2a * P[mi][ni][0];
                Z[mi][ni][1] += c2a * P[mi][ni][1];
                Z[mi][ni][2] += c2b * P[mi][ni][2];
                Z[mi][ni][3] += c2b * P[mi][ni][3];
                P[mi][ni][0] = 0.f; P[mi][ni][1] = 0.f;
                P[mi][ni][2] = 0.f; P[mi][ni][3] = 0.f;
            }
        }
        __syncthreads();
        if (s + 2 <= 6) ldstage(s + 2);
    }

    asm volatile("cp.async.wait_group 0;" ::: "memory");

    // store Y,Z (fp16) to smem
#pragma unroll
    for (int mi = 0; mi < 2; mi++) {
        int row = wm * 32 + mi * 16 + g;
#pragma unroll
        for (int ni = 0; ni < 4; ni++) {
            int col = wn * 32 + ni * 8 + tg * 2;
            *reinterpret_cast<__half2*>(Yz + row * STR + col) =
                __floats2half2_rn(Y[mi][ni][0], Y[mi][ni][1]);
            *reinterpret_cast<__half2*>(Yz + (row + 8) * STR + col) =
                __floats2half2_rn(Y[mi][ni][2], Y[mi][ni][3]);
            *reinterpret_cast<__half2*>(Yz + 64 * STR + row * STR + col) =
                __floats2half2_rn(Z[mi][ni][0], Z[mi][ni][1]);
            *reinterpret_cast<__half2*>(Yz + 64 * STR + (row + 8) * STR + col) =
                __floats2half2_rn(Z[mi][ni][2], Z[mi][ni][3]);
        }
    }
    __syncthreads();

    // stage 2: out = Yh@Wc1^T + Zh@Wc2^T   (P reused as accumulator, already zero)
    mmastep(Yz, Bw);                 // Y @ Wc1^T
    mmastep(Yz + 64 * STR, Wc2s);    // Z @ Wc2^T

    // epilogue: + 6*bc
#pragma unroll
    for (int mi = 0; mi < 2; mi++) {
        int ra = n0 + wm * 32 + mi * 16 + g;
#pragma unroll
        for (int ni = 0; ni < 4; ni++) {
            int col = wn * 32 + ni * 8 + tg * 2;
            float b0 = 6.0f * bc[col];
            float b1 = 6.0f * bc[col + 1];
            if (ra < NN) {
                float2 v = make_float2(P[mi][ni][0] + b0, P[mi][ni][1] + b1);
                *reinterpret_cast<float2*>(&out[(size_t)ra * FF + col]) = v;
            }
            if (ra + 8 < NN) {
                float2 v = make_float2(P[mi][ni][2] + b0, P[mi][ni][3] + b1);
                *reinterpret_cast<float2*>(&out[(size_t)(ra + 8) * FF + col]) = v;
            }
        }
    }
}

// ---------------- launch ----------------
extern "C" void kernel_launch(void* const* d_in, const int* in_sizes, int n_in,
                              void* d_out, int out_size) {
    const float* node_h = (const float*)d_in[0];
    const float* W      = (const float*)d_in[1];
    const float* att1   = (const float*)d_in[2];
    const float* att2   = (const float*)d_in[3];
    const float* Wc     = (const float*)d_in[4];
    const float* bc     = (const float*)d_in[5];
    const int*   esrc   = (const int*)d_in[6];
    const int*   edst   = (const int*)d_in[7];
    const int*   erel   = (const int*)d_in[8];
    float* out = (float*)d_out;

    static int smem_set = 0;
    if (!smem_set) {
        cudaFuncSetAttribute(gemm_kernel, cudaFuncAttributeMaxDynamicSharedMemorySize, GEMM_SMEM);
        smem_set = 1;
    }

    const int nblk1 = (SEG + 511) / 512;

    precompute_kernel<<<RR * FF, 128>>>(W, att1, att2);
    wc_convert_kernel<<<FF, 128>>>(Wc);
    nodeh_convert_kernel<<<(NN * FF / 8 + 255) / 256, 256>>>(node_h);
    zero_cnt_kernel<<<(SEG + 255) / 256, 256>>>();
    hist_kernel<<<(EE + 255) / 256, 256>>>(edst, erel);
    scan1_kernel<<<nblk1, 512>>>();
    scan2_kernel<<<1, 1024>>>(nblk1);
    scan3_kernel<<<(SEG + 255) / 256, 256>>>();
    permute_kernel<<<(EE + 255) / 256, 256>>>(esrc, edst, erel);
    gather_kernel<<<(SEG + 7) / 8, 256>>>();
    softmax_kernel<<<(NN + 255) / 256, 256>>>();
    gemm_kernel<<<(NN + 63) / 64, 256, GEMM_SMEM>>>(out, bc);

    if (out_size >= NN * FF + RR * FF * FF) {
        cudaMemcpyAsync(out + (size_t)NN * FF, W,
                        sizeof(float) * RR * FF * FF, cudaMemcpyDeviceToDevice, 0);
    }
}